// round 15
// baseline (speedup 1.0000x reference)
#include <cuda_runtime.h>
#include <cuda_bf16.h>
#include <cooperative_groups.h>
#include <math.h>

namespace cg = cooperative_groups;

#define Bsz 32
#define Ssz 1024
#define Hsz 256
#define G4  1024
#define KS  204        // W_hh^T k-slices in SMEM (multiple of 4)
#define KR  52         // W_hh^T k-slices in registers (KS+KR = 256)

// static scratch
__device__ float         g_WX[(size_t)Bsz * Ssz * G4];   // enc@W_ih^T + biases
__device__ float         g_H [(size_t)Bsz * Ssz * Hsz];  // h(t+1) history
__device__ __nv_bfloat16 g_encT[(size_t)Bsz * Hsz * Ssz];// encT[b][k][s]
__device__ float         g_WT[Hsz * G4];                 // W_hh^T [k][j]
__device__ float         g_D[Bsz * Ssz];                 // sound per-row err coeff

__device__ __forceinline__ float dot8(float4 a0, float4 a1, float4 h0, float4 h1) {
  return a0.x*h0.x + a0.y*h0.y + a0.z*h0.z + a0.w*h0.w
       + a1.x*h1.x + a1.y*h1.y + a1.z*h1.z + a1.w*h1.w;
}
__device__ __forceinline__ float wsum(float acc) {
#pragma unroll
  for (int o = 16; o; o >>= 1) acc += __shfl_down_sync(0xffffffffu, acc, o);
  return acc;
}
__device__ __forceinline__ void acc8(float* a, uint4 u, float hv) {
  a[0] += __uint_as_float(u.x << 16)          * hv;
  a[1] += __uint_as_float(u.x & 0xFFFF0000u)  * hv;
  a[2] += __uint_as_float(u.y << 16)          * hv;
  a[3] += __uint_as_float(u.y & 0xFFFF0000u)  * hv;
  a[4] += __uint_as_float(u.z << 16)          * hv;
  a[5] += __uint_as_float(u.z & 0xFFFF0000u)  * hv;
  a[6] += __uint_as_float(u.w << 16)          * hv;
  a[7] += __uint_as_float(u.w & 0xFFFF0000u)  * hv;
}

#define CL_ARRIVE() asm volatile("barrier.cluster.arrive.aligned;" ::: "memory")
#define CL_WAIT()   asm volatile("barrier.cluster.wait.aligned;"   ::: "memory")

#define LDG4(buf, base, g) do { \
  buf[0] = base[((g)*4+0)*128]; buf[1] = base[((g)*4+1)*128]; \
  buf[2] = base[((g)*4+2)*128]; buf[3] = base[((g)*4+3)*128]; } while (0)
#define PROC4(a, buf, hq) do { \
  acc8(a, buf[0], (hq).x); acc8(a, buf[1], (hq).y); \
  acc8(a, buf[2], (hq).z); acc8(a, buf[3], (hq).w); } while (0)

// ---------------------------------------------------------------------------
// Kernel 1: WX = enc @ W_ih^T + (b_ih + b_hh), fused with norm + bf16-delta
// norm computation for the sound score-error coefficient D_s.
// ---------------------------------------------------------------------------
__global__ __launch_bounds__(256) void wx_gemm(
    const float* __restrict__ A, const float* __restrict__ Wb,
    const float* __restrict__ b_ih, const float* __restrict__ b_hh)
{
  __shared__ float As[16][64];
  __shared__ float Bs[16][64];
  __shared__ float norm2[64];
  __shared__ float dnorm2[64];
  const int tid = threadIdx.x;
  const int row0 = blockIdx.y * 64, col0 = blockIdx.x * 64;
  const int lr = tid >> 2, lc = (tid & 3) * 4;
  const int ty = tid >> 4, tx = tid & 15;
  float acc[4][4] = {};
  if (tid < 64) { norm2[tid] = 0.f; dnorm2[tid] = 0.f; }
  __syncthreads();
  for (int k0 = 0; k0 < 256; k0 += 16) {
    float4 av = *(const float4*)(A  + (size_t)(row0 + lr) * 256 + k0 + lc);
    float4 bv = *(const float4*)(Wb + (size_t)(col0 + lr) * 256 + k0 + lc);
    float dx = av.x - __bfloat162float(__float2bfloat16_rn(av.x));
    float dy = av.y - __bfloat162float(__float2bfloat16_rn(av.y));
    float dz = av.z - __bfloat162float(__float2bfloat16_rn(av.z));
    float dw = av.w - __bfloat162float(__float2bfloat16_rn(av.w));
    atomicAdd(&norm2[lr],  av.x*av.x + av.y*av.y + av.z*av.z + av.w*av.w);
    atomicAdd(&dnorm2[lr], dx*dx + dy*dy + dz*dz + dw*dw);
    As[lc+0][lr]=av.x; As[lc+1][lr]=av.y; As[lc+2][lr]=av.z; As[lc+3][lr]=av.w;
    Bs[lc+0][lr]=bv.x; Bs[lc+1][lr]=bv.y; Bs[lc+2][lr]=bv.z; Bs[lc+3][lr]=bv.w;
    __syncthreads();
#pragma unroll
    for (int kk = 0; kk < 16; kk++) {
      float4 a4 = *(const float4*)&As[kk][ty*4];
      float4 b4 = *(const float4*)&Bs[kk][tx*4];
      float a[4]={a4.x,a4.y,a4.z,a4.w}, bb[4]={b4.x,b4.y,b4.z,b4.w};
#pragma unroll
      for (int i = 0; i < 4; i++)
#pragma unroll
        for (int j = 0; j < 4; j++) acc[i][j] += a[i]*bb[j];
    }
    __syncthreads();
  }
#pragma unroll
  for (int i = 0; i < 4; i++) {
    int rr = row0 + ty*4 + i;
#pragma unroll
    for (int j = 0; j < 4; j++) {
      int cc = col0 + tx*4 + j;
      g_WX[(size_t)rr * G4 + cc] = acc[i][j] + b_ih[cc] + b_hh[cc];
    }
  }
  // D_s = 1.02*||enc_s - bf16(enc_s)|| + 1e-5*||enc_s||  (sound, ~2x tighter)
  if (tid < 64)
    g_D[row0 + tid] = 1.02f * sqrtf(dnorm2[tid]) + 1e-5f * sqrtf(norm2[tid]);
}

// ---------------------------------------------------------------------------
// Kernel 1b: post-loop scores GEMM  out[b][t][s] = g_H[b][t]·enc[b][s]
// ---------------------------------------------------------------------------
__global__ __launch_bounds__(256) void score_gemm(
    const float* __restrict__ enc, float* __restrict__ out)
{
  __shared__ float As[16][64];
  __shared__ float Bs[16][64];
  const int bz = blockIdx.z;
  const float* A  = g_H + (size_t)bz * Ssz * Hsz;
  const float* Bm = enc + (size_t)bz * Ssz * Hsz;
  float* C = out + (size_t)bz * Ssz * Ssz;
  const int tid = threadIdx.x;
  const int row0 = blockIdx.y * 64, col0 = blockIdx.x * 64;
  const int lr = tid >> 2, lc = (tid & 3) * 4;
  const int ty = tid >> 4, tx = tid & 15;
  float acc[4][4] = {};
  for (int k0 = 0; k0 < 256; k0 += 16) {
    float4 av = *(const float4*)(A  + (size_t)(row0 + lr) * 256 + k0 + lc);
    float4 bv = *(const float4*)(Bm + (size_t)(col0 + lr) * 256 + k0 + lc);
    As[lc+0][lr]=av.x; As[lc+1][lr]=av.y; As[lc+2][lr]=av.z; As[lc+3][lr]=av.w;
    Bs[lc+0][lr]=bv.x; Bs[lc+1][lr]=bv.y; Bs[lc+2][lr]=bv.z; Bs[lc+3][lr]=bv.w;
    __syncthreads();
#pragma unroll
    for (int kk = 0; kk < 16; kk++) {
      float4 a4 = *(const float4*)&As[kk][ty*4];
      float4 b4 = *(const float4*)&Bs[kk][tx*4];
      float a[4]={a4.x,a4.y,a4.z,a4.w}, bb[4]={b4.x,b4.y,b4.z,b4.w};
#pragma unroll
      for (int i = 0; i < 4; i++)
#pragma unroll
        for (int j = 0; j < 4; j++) acc[i][j] += a[i]*bb[j];
    }
    __syncthreads();
  }
#pragma unroll
  for (int i = 0; i < 4; i++)
#pragma unroll
    for (int j = 0; j < 4; j++)
      C[(size_t)(row0 + ty*4 + i) * Ssz + col0 + tx*4 + j] = acc[i][j];
}

// ---------------------------------------------------------------------------
// Prep kernels
// ---------------------------------------------------------------------------
__global__ void enc_bf_T(const float* __restrict__ enc) {
  __shared__ float tile[32][33];
  const int b = blockIdx.z, s0 = blockIdx.x * 32, k0 = blockIdx.y * 32;
  const int tx = threadIdx.x, ty = threadIdx.y;
  const float* eb = enc + (size_t)b * Ssz * Hsz;
#pragma unroll
  for (int i = 0; i < 32; i += 8)
    tile[ty + i][tx] = eb[(size_t)(s0 + ty + i) * Hsz + k0 + tx];
  __syncthreads();
  __nv_bfloat16* ob = g_encT + (size_t)b * Hsz * Ssz;
#pragma unroll
  for (int i = 0; i < 32; i += 8)
    ob[(size_t)(k0 + ty + i) * Ssz + s0 + tx] = __float2bfloat16_rn(tile[tx][ty + i]);
}

__global__ void whh_T(const float* __restrict__ W_hh) {
  __shared__ float tile[32][33];
  const int j0 = blockIdx.x * 32, k0 = blockIdx.y * 32;
  const int tx = threadIdx.x, ty = threadIdx.y;
#pragma unroll
  for (int i = 0; i < 32; i += 8)
    tile[ty + i][tx] = W_hh[(size_t)(j0 + ty + i) * Hsz + k0 + tx];
  __syncthreads();
#pragma unroll
  for (int i = 0; i < 32; i += 8)
    g_WT[(size_t)(k0 + ty + i) * G4 + j0 + tx] = tile[tx][ty + i];
}

// ---------------------------------------------------------------------------
// Kernel 2: sequential decoder. One 4-CTA cluster per batch.
// warps 0-7: bf16 scores + reduce; warps 8-15: gates GEMV + cell.
// One cluster sync per step; scores warps pre-issue next step's enc loads
// during the cell (enc addresses are loop-invariant).
// ---------------------------------------------------------------------------
__global__ void __cluster_dims__(4, 1, 1) __launch_bounds__(512, 1)
decoder_main(const float* __restrict__ enc,
             const float* __restrict__ b_ih,
             const float* __restrict__ b_hh)
{
  extern __shared__ float sm[];
  float*  Wt        = sm;                     // KS*256 packed [k4][j][4]
  float*  h_s       = Wt + KS * 256;          // 256 (full h, local)
  float*  c_s       = h_s + 256;              // 256 (full c, local)
  float*  gates_all = c_s + 256;              // [2][1024] parity-buffered
  float*  scores_s  = gates_all + 2048;       // 256
  float*  sp        = scores_s + 256;         // 8*256 partials [kc][s]
  float*  n_sm      = sp + 2048;              // 256 (D_s per owned row)
  float*  normh_s   = n_sm + 256;             // 4
  float4* redA      = (float4*)(normh_s + 4); // 8 (u1,u2,lb,i1)
  float*  red_m     = (float*)(redA + 8);     // 8
  int*    red_i     = (int*)(red_m + 8);      // 8
  float4* tup1      = (float4*)(red_i + 8);   // [2][4]
  float*  tup2m     = (float*)(tup1 + 8);     // [2][4]
  int*    tup2i     = (int*)(tup2m + 8);      // [2][4]

  cg::cluster_group cluster = cg::this_cluster();
  const int tid  = threadIdx.x;
  const int w    = tid >> 5, lane = tid & 31;
  const int r    = blockIdx.x & 3;
  const int b    = blockIdx.x >> 2;

  // ---- init: W^T SMEM packed [k4][j][4]; CTA-owned gate cols ----
  for (int i = tid; i < KS * 256; i += 512) {
    int k = i >> 8, j = i & 255;
    int G = (j >> 6) * 256 + r * 64 + (j & 63);
    Wt[(size_t)((k >> 2) * 256 + j) * 4 + (k & 3)] = g_WT[(size_t)k * G4 + G];
  }
  float wreg[KR];
  const int jloc = (w - 8) * 32 + lane;
  const int Gj   = (jloc >> 6) * 256 + r * 64 + (jloc & 63);  // global gate idx
  if (w >= 8) {
#pragma unroll
    for (int kk = 0; kk < KR; kk++)
      wreg[kk] = g_WT[(size_t)(KS + kk) * G4 + Gj];
  }
  if (tid < 256) n_sm[tid] = g_D[b * Ssz + r * 256 + tid];

  // ---- prologue: full h(1), c(1) from bias-only gates ----
  if (tid < 256) {
    float gi = b_ih[tid]       + b_hh[tid];
    float gg = b_ih[512 + tid] + b_hh[512 + tid];
    float go = b_ih[768 + tid] + b_hh[768 + tid];
    float iv = 1.f / (1.f + expf(-gi));
    float gv = tanhf(gg);
    float ov = 1.f / (1.f + expf(-go));
    float c  = iv * gv;
    c_s[tid] = c;
    h_s[tid] = ov * tanhf(c);
  }
  __syncthreads();
  if (tid < 256 && (tid >> 6) == r)
    g_H[(size_t)b * Ssz * Hsz + tid] = h_s[tid];
  CL_ARRIVE(); CL_WAIT();   // cluster fully resident before DSMEM traffic

  const float* WXb  = g_WX + (size_t)b * Ssz * G4;
  const float* encb = enc + (size_t)b * Ssz * Hsz;

  // enc bf16 stream + permanent register cache of k-groups 0,1
  const uint4* pb = (const uint4*)(g_encT + (size_t)(b * Hsz + w * 32) * Ssz)
                    + r * 32 + lane;
  uint4 pf[8];
  uint4 bA[4], bB[4], bC[4];
  if (w < 8) {
#pragma unroll
    for (int q = 0; q < 8; q++) pf[q] = pb[q * 128];
    LDG4(bA, pb, 2); LDG4(bB, pb, 3); LDG4(bC, pb, 4);   // prologue pre-issue
  }

  int idx = 0;

#pragma unroll 1
  for (int t = 0; t < Ssz; t++) {
    const int tp = t & 1;
    const float4* hp4 = (const float4*)h_s;

    if (w < 8) {
      // ---- bf16 scores: groups 0,1 from regs; 2-4 pre-issued last step ----
      float a[8] = {0.f,0.f,0.f,0.f,0.f,0.f,0.f,0.f};
      float4 hq;
      hq = hp4[w*8+0]; PROC4(a, (pf+0), hq);
      hq = hp4[w*8+1]; PROC4(a, (pf+4), hq);
      hq = hp4[w*8+2]; PROC4(a, bA, hq); LDG4(bA, pb, 5);
      hq = hp4[w*8+3]; PROC4(a, bB, hq); LDG4(bB, pb, 6);
      hq = hp4[w*8+4]; PROC4(a, bC, hq); LDG4(bC, pb, 7);
      hq = hp4[w*8+5]; PROC4(a, bA, hq);
      hq = hp4[w*8+6]; PROC4(a, bB, hq);
      hq = hp4[w*8+7]; PROC4(a, bC, hq);
      float4* spv = (float4*)(sp + w * 256 + lane * 8);
      spv[0] = make_float4(a[0], a[1], a[2], a[3]);
      spv[1] = make_float4(a[4], a[5], a[6], a[7]);
    } else {
      if (w == 15) {             // ||h|| for the error bound
        float s2 = 0.f;
#pragma unroll
        for (int q = 0; q < 8; q++) { float hv = h_s[lane + 32*q]; s2 += hv*hv; }
        s2 = wsum(s2);
        if (lane == 0) normh_s[0] = sqrtf(s2) * 1.01f;
      }
      // ---- fp32 gates (accumulation order bit-identical to R9) ----
      const float4* Wj = (const float4*)Wt + jloc;
      float acc0 = 0.f, acc1 = 0.f;
#pragma unroll 6
      for (int k4 = 0; k4 < KS / 4; k4++) {
        float4 wv = Wj[(size_t)k4 * 256];
        float4 hv = hp4[k4];
        acc0 += wv.x * hv.x;  acc1 += wv.y * hv.y;
        acc0 += wv.z * hv.z;  acc1 += wv.w * hv.w;
      }
#pragma unroll
      for (int q = 0; q < KR / 4; q++) {
        float4 hv = hp4[KS / 4 + q];
        acc0 += wreg[4*q + 0] * hv.x;  acc1 += wreg[4*q + 1] * hv.y;
        acc0 += wreg[4*q + 2] * hv.z;  acc1 += wreg[4*q + 3] * hv.w;
      }
      float gv_ = acc0 + acc1;
      // publish: local STS + 3 rotated remote DSMEM stores
      gates_all[tp * 1024 + Gj] = gv_;
      float* gp = &gates_all[tp * 1024 + Gj];
#pragma unroll
      for (int q = 1; q < 4; q++)
        *cluster.map_shared_rank(gp, (r + q) & 3) = gv_;
    }
    __syncthreads();

    // ---- per-CTA top-2(ub) + max(lb) over 256 s ----
    if (tid < 256) {
      const int s = tid;
      float scv = 0.f;
#pragma unroll
      for (int q = 0; q < 8; q++) scv += sp[q * 256 + s];
      scores_s[s] = scv;
      float E  = n_sm[s] * normh_s[0];
      float lb = scv - E;
      float u1 = scv + E, u2 = -INFINITY; int i1 = s;
#pragma unroll
      for (int o = 16; o; o >>= 1) {
        float ou1 = __shfl_xor_sync(0xffffffffu, u1, o);
        float ou2 = __shfl_xor_sync(0xffffffffu, u2, o);
        int   oi1 = __shfl_xor_sync(0xffffffffu, i1, o);
        float olb = __shfl_xor_sync(0xffffffffu, lb, o);
        lb = fmaxf(lb, olb);
        if (ou1 > u1) { u2 = fmaxf(u1, ou2); u1 = ou1; i1 = oi1; }
        else { u2 = fmaxf(u2, ou1); if (ou1 == u1) i1 = min(i1, oi1); }
      }
      if (lane == 0) redA[w] = make_float4(u1, u2, lb, __int_as_float(i1));
    }
    __syncthreads();

    // warp 14 (gates warp, idle): merge local winner, prefetch its full 4KB
    // WX row to L1+L2 (winner is always one of the 4 local winners; for this
    // CTA the L1 copy serves the cell directly).
    if (w == 14 && t < Ssz - 1) {
      float u1 = -INFINITY; int i1 = 0;
      if (lane < 8) { float4 tq = redA[lane]; u1 = tq.x; i1 = __float_as_int(tq.w); }
#pragma unroll
      for (int o = 4; o; o >>= 1) {
        float ou = __shfl_down_sync(0xffffffffu, u1, o);
        int   oi = __shfl_down_sync(0xffffffffu, i1, o);
        if (ou > u1) { u1 = ou; i1 = oi; }
      }
      i1 = __shfl_sync(0xffffffffu, i1, 0);
      const char* rowp = (const char*)(WXb + (size_t)(r * 256 + i1) * G4);
      asm volatile("prefetch.global.L2 [%0];" :: "l"(rowp + lane * 128));
      asm volatile("prefetch.global.L1 [%0];" :: "l"(rowp + lane * 128));
    }
    if (tid == 0) {
      float4 t0 = redA[0];
      float u1 = t0.x, u2 = t0.y, lbm = t0.z; int i1 = __float_as_int(t0.w);
#pragma unroll
      for (int q = 1; q < 8; q++) {
        float4 tq = redA[q];
        lbm = fmaxf(lbm, tq.z);
        float ou1 = tq.x, ou2 = tq.y; int oi1 = __float_as_int(tq.w);
        if (ou1 > u1) { u2 = fmaxf(u1, ou2); u1 = ou1; i1 = oi1; }
        else { u2 = fmaxf(u2, ou1); if (ou1 == u1) i1 = min(i1, oi1); }
      }
      float4 pub = make_float4(u1, u2, lbm, __int_as_float(r * 256 + i1));
#pragma unroll
      for (int dst = 0; dst < 4; dst++)
        *cluster.map_shared_rank(&tup1[tp * 4 + r], dst) = pub;
    }
    CL_ARRIVE(); CL_WAIT();   // single per-step cluster sync: gates + tuples

    // ---- decide argmax (fast: unique candidate; slow: fp32 rescore) ----
    float4 q0 = tup1[tp*4+0], q1 = tup1[tp*4+1];
    float4 q2 = tup1[tp*4+2], q3 = tup1[tp*4+3];
    float L = fmaxf(fmaxf(q0.z, q1.z), fmaxf(q2.z, q3.z));
    float u1a[4] = {q0.x, q1.x, q2.x, q3.x};
    float u2a[4] = {q0.y, q1.y, q2.y, q3.y};
    float i1a[4] = {q0.w, q1.w, q2.w, q3.w};
    int cnt = 0, rstar = 0;
#pragma unroll
    for (int q = 3; q >= 0; q--)
      if (u1a[q] >= L) { cnt++; rstar = q; }
    bool fast = (cnt == 1) && (u2a[rstar] < L);

    if (fast) {
      idx = __float_as_int(i1a[rstar]);
    } else if (t < Ssz - 1) {
      // slow path (uniform cluster-wide): fp32 rescore of candidates
      if (w < 8) {
        const int s = tid;
        float E  = n_sm[s] * normh_s[0];
        float ub = scores_s[s] + E;
        unsigned mask = __ballot_sync(0xffffffffu, ub >= L);
        float best = -INFINITY; int bidx = 0x7fffffff;
        float4 h0w = hp4[lane], h1w = hp4[32 + lane];
        while (mask) {
          int bit = __ffs(mask) - 1; mask &= mask - 1;
          int s0 = w * 32 + bit;
          const float4* er = (const float4*)(encb + (size_t)(r * 256 + s0) * Hsz);
          float val = wsum(dot8(er[lane], er[32 + lane], h0w, h1w));
          if (lane == 0 && val > best) { best = val; bidx = s0; }
        }
        if (lane == 0) {
          red_m[w] = best;
          red_i[w] = (bidx == 0x7fffffff) ? 0x7fffffff : r * 256 + bidx;
        }
      }
      __syncthreads();
      if (tid == 0) {
        float gv = red_m[0]; int gi = red_i[0];
#pragma unroll
        for (int q = 1; q < 8; q++) {
          float v = red_m[q]; int ii = red_i[q];
          if (v > gv || (v == gv && ii < gi)) { gv = v; gi = ii; }
        }
#pragma unroll
        for (int dst = 0; dst < 4; dst++) {
          *cluster.map_shared_rank(&tup2m[tp * 4 + r], dst) = gv;
          *cluster.map_shared_rank(&tup2i[tp * 4 + r], dst) = gi;
        }
      }
      CL_ARRIVE(); CL_WAIT();
      float gm = tup2m[tp * 4 + 0]; idx = tup2i[tp * 4 + 0];
#pragma unroll
      for (int q = 1; q < 4; q++) {
        float mq = tup2m[tp * 4 + q]; int iq = tup2i[tp * 4 + q];
        if (mq > gm || (mq == gm && iq < idx)) { gm = mq; idx = iq; }
      }
    }

    // ---- scores warps pre-issue next step's enc groups (h-independent) ----
    if (w < 8) { LDG4(bA, pb, 2); LDG4(bB, pb, 3); LDG4(bC, pb, 4); }

    // ---- full cell on gates warps (tid>=256): h stays CTA-local ----
    if (t < Ssz - 1) {
      if (tid >= 256) {
        int j = tid - 256;
        const float* ga  = gates_all + tp * 1024;
        const float* wxr = WXb + (size_t)idx * G4 + j;
        float gi = ga[j]        + wxr[0];
        float gf = ga[256 + j]  + wxr[256];
        float gg = ga[512 + j]  + wxr[512];
        float go = ga[768 + j]  + wxr[768];
        float iv = 1.f / (1.f + expf(-gi));
        float fv = 1.f / (1.f + expf(-gf));
        float gv = tanhf(gg);
        float ov = 1.f / (1.f + expf(-go));
        float c  = fv * c_s[j] + iv * gv;
        c_s[j] = c;
        float hk = ov * tanhf(c);
        h_s[j] = hk;
        if ((j >> 6) == r)
          g_H[((size_t)b * Ssz + t + 1) * Hsz + j] = hk;
      }
      __syncthreads();   // h_s/c_s ready for next step (CTA-local)
    }
  }
}

// ---------------------------------------------------------------------------
// Kernel 4: softmax over out rows
// ---------------------------------------------------------------------------
__global__ __launch_bounds__(256) void softmax_finalize(float* __restrict__ out)
{
  __shared__ float rmx[8];
  __shared__ float rsm[8];
  const int tid = threadIdx.x, w = tid >> 5, lane = tid & 31;
  float4* row = (float4*)(out + (size_t)blockIdx.x * Ssz);
  float4 v = row[tid];
  float m = fmaxf(fmaxf(v.x, v.y), fmaxf(v.z, v.w));
#pragma unroll
  for (int o = 16; o; o >>= 1) m = fmaxf(m, __shfl_xor_sync(0xffffffffu, m, o));
  if (lane == 0) rmx[w] = m;
  __syncthreads();
  m = rmx[0];
#pragma unroll
  for (int q = 1; q < 8; q++) m = fmaxf(m, rmx[q]);
  float4 e;
  e.x = expf(v.x - m); e.y = expf(v.y - m);
  e.z = expf(v.z - m); e.w = expf(v.w - m);
  float s = (e.x + e.y) + (e.z + e.w);
#pragma unroll
  for (int o = 16; o; o >>= 1) s += __shfl_xor_sync(0xffffffffu, s, o);
  if (lane == 0) rsm[w] = s;
  __syncthreads();
  s = 0.f;
#pragma unroll
  for (int q = 0; q < 8; q++) s += rsm[q];
  float inv = 1.f / s;
  e.x *= inv; e.y *= inv; e.z *= inv; e.w *= inv;
  row[tid] = e;
}

// ---------------------------------------------------------------------------
extern "C" void kernel_launch(void* const* d_in, const int* in_sizes, int n_in,
                              void* d_out, int out_size)
{
  const float* enc  = (const float*)d_in[0];
  const float* W_ih = (const float*)d_in[1];
  const float* W_hh = (const float*)d_in[2];
  const float* b_ih = (const float*)d_in[3];
  const float* b_hh = (const float*)d_in[4];
  float* out = (float*)d_out;

  // preps (decoder at launch index 3 so the ncu window lands on it)
  enc_bf_T<<<dim3(Ssz / 32, Hsz / 32, Bsz), dim3(32, 8)>>>(enc);
  whh_T<<<dim3(G4 / 32, Hsz / 32), dim3(32, 8)>>>(W_hh);
  dim3 g1(G4 / 64, (Bsz * Ssz) / 64);
  wx_gemm<<<g1, 256>>>(enc, W_ih, b_ih, b_hh);

  // sequential decoder: 32 clusters x 4 CTAs x 512 threads
  const int smem_bytes = (KS * 256 + 256 + 256 + 2048 + 256 + 2048 + 256 + 4
                          + 8 * 4 + 8 + 8 + 8 * 4 + 8 + 8) * 4;
  cudaFuncSetAttribute(decoder_main,
                       cudaFuncAttributeMaxDynamicSharedMemorySize, smem_bytes);
  decoder_main<<<Bsz * 4, 512, smem_bytes>>>(enc, b_ih, b_hh);

  // probs off the critical path
  score_gemm<<<dim3(Ssz / 64, Ssz / 64, Bsz), 256>>>(enc, out);
  softmax_finalize<<<Bsz * Ssz, 256>>>(out);
}

// round 16
// speedup vs baseline: 1.1660x; 1.1660x over previous
#include <cuda_runtime.h>
#include <cuda_bf16.h>
#include <cooperative_groups.h>
#include <math.h>

namespace cg = cooperative_groups;

#define Bsz 32
#define Ssz 1024
#define Hsz 256
#define G4  1024
#define KS  204        // W_hh^T k-slices in SMEM (multiple of 4)
#define KR  52         // W_hh^T k-slices in registers (KS+KR = 256)

// static scratch
__device__ float         g_WX[(size_t)Bsz * Ssz * G4];   // enc@W_ih^T + biases
__device__ float         g_H [(size_t)Bsz * Ssz * Hsz];  // h(t+1) history
__device__ __nv_bfloat16 g_encT[(size_t)Bsz * Hsz * Ssz];// encT[b][k][s]
__device__ float         g_WT[Hsz * G4];                 // W_hh^T [k][j]
__device__ float         g_D[Bsz * Ssz];                 // sound per-row err coeff

__device__ __forceinline__ float dot8(float4 a0, float4 a1, float4 h0, float4 h1) {
  return a0.x*h0.x + a0.y*h0.y + a0.z*h0.z + a0.w*h0.w
       + a1.x*h1.x + a1.y*h1.y + a1.z*h1.z + a1.w*h1.w;
}
__device__ __forceinline__ float wsum(float acc) {
#pragma unroll
  for (int o = 16; o; o >>= 1) acc += __shfl_down_sync(0xffffffffu, acc, o);
  return acc;
}
__device__ __forceinline__ void acc8(float* a, uint4 u, float hv) {
  a[0] += __uint_as_float(u.x << 16)          * hv;
  a[1] += __uint_as_float(u.x & 0xFFFF0000u)  * hv;
  a[2] += __uint_as_float(u.y << 16)          * hv;
  a[3] += __uint_as_float(u.y & 0xFFFF0000u)  * hv;
  a[4] += __uint_as_float(u.z << 16)          * hv;
  a[5] += __uint_as_float(u.z & 0xFFFF0000u)  * hv;
  a[6] += __uint_as_float(u.w << 16)          * hv;
  a[7] += __uint_as_float(u.w & 0xFFFF0000u)  * hv;
}

#define CL_ARRIVE() asm volatile("barrier.cluster.arrive.aligned;" ::: "memory")
#define CL_WAIT()   asm volatile("barrier.cluster.wait.aligned;"   ::: "memory")

#define LDG4(buf, base, g) do { \
  buf[0] = base[((g)*4+0)*128]; buf[1] = base[((g)*4+1)*128]; \
  buf[2] = base[((g)*4+2)*128]; buf[3] = base[((g)*4+3)*128]; } while (0)
#define PROC4(a, buf, hq) do { \
  acc8(a, buf[0], (hq).x); acc8(a, buf[1], (hq).y); \
  acc8(a, buf[2], (hq).z); acc8(a, buf[3], (hq).w); } while (0)

// ---------------------------------------------------------------------------
// Kernel 1: WX = enc @ W_ih^T + (b_ih + b_hh), fused with norm + bf16-delta
// norm computation for the sound score-error coefficient D_s.
// ---------------------------------------------------------------------------
__global__ __launch_bounds__(256) void wx_gemm(
    const float* __restrict__ A, const float* __restrict__ Wb,
    const float* __restrict__ b_ih, const float* __restrict__ b_hh)
{
  __shared__ float As[16][64];
  __shared__ float Bs[16][64];
  __shared__ float norm2[64];
  __shared__ float dnorm2[64];
  const int tid = threadIdx.x;
  const int row0 = blockIdx.y * 64, col0 = blockIdx.x * 64;
  const int lr = tid >> 2, lc = (tid & 3) * 4;
  const int ty = tid >> 4, tx = tid & 15;
  float acc[4][4] = {};
  if (tid < 64) { norm2[tid] = 0.f; dnorm2[tid] = 0.f; }
  __syncthreads();
  for (int k0 = 0; k0 < 256; k0 += 16) {
    float4 av = *(const float4*)(A  + (size_t)(row0 + lr) * 256 + k0 + lc);
    float4 bv = *(const float4*)(Wb + (size_t)(col0 + lr) * 256 + k0 + lc);
    float dx = av.x - __bfloat162float(__float2bfloat16_rn(av.x));
    float dy = av.y - __bfloat162float(__float2bfloat16_rn(av.y));
    float dz = av.z - __bfloat162float(__float2bfloat16_rn(av.z));
    float dw = av.w - __bfloat162float(__float2bfloat16_rn(av.w));
    atomicAdd(&norm2[lr],  av.x*av.x + av.y*av.y + av.z*av.z + av.w*av.w);
    atomicAdd(&dnorm2[lr], dx*dx + dy*dy + dz*dz + dw*dw);
    As[lc+0][lr]=av.x; As[lc+1][lr]=av.y; As[lc+2][lr]=av.z; As[lc+3][lr]=av.w;
    Bs[lc+0][lr]=bv.x; Bs[lc+1][lr]=bv.y; Bs[lc+2][lr]=bv.z; Bs[lc+3][lr]=bv.w;
    __syncthreads();
#pragma unroll
    for (int kk = 0; kk < 16; kk++) {
      float4 a4 = *(const float4*)&As[kk][ty*4];
      float4 b4 = *(const float4*)&Bs[kk][tx*4];
      float a[4]={a4.x,a4.y,a4.z,a4.w}, bb[4]={b4.x,b4.y,b4.z,b4.w};
#pragma unroll
      for (int i = 0; i < 4; i++)
#pragma unroll
        for (int j = 0; j < 4; j++) acc[i][j] += a[i]*bb[j];
    }
    __syncthreads();
  }
#pragma unroll
  for (int i = 0; i < 4; i++) {
    int rr = row0 + ty*4 + i;
#pragma unroll
    for (int j = 0; j < 4; j++) {
      int cc = col0 + tx*4 + j;
      g_WX[(size_t)rr * G4 + cc] = acc[i][j] + b_ih[cc] + b_hh[cc];
    }
  }
  // D_s = 1.02*||enc_s - bf16(enc_s)|| + 1e-5*||enc_s||  (sound, ~2x tighter)
  if (tid < 64)
    g_D[row0 + tid] = 1.02f * sqrtf(dnorm2[tid]) + 1e-5f * sqrtf(norm2[tid]);
}

// ---------------------------------------------------------------------------
// Kernel 1b: post-loop scores GEMM  out[b][t][s] = g_H[b][t]·enc[b][s]
// ---------------------------------------------------------------------------
__global__ __launch_bounds__(256) void score_gemm(
    const float* __restrict__ enc, float* __restrict__ out)
{
  __shared__ float As[16][64];
  __shared__ float Bs[16][64];
  const int bz = blockIdx.z;
  const float* A  = g_H + (size_t)bz * Ssz * Hsz;
  const float* Bm = enc + (size_t)bz * Ssz * Hsz;
  float* C = out + (size_t)bz * Ssz * Ssz;
  const int tid = threadIdx.x;
  const int row0 = blockIdx.y * 64, col0 = blockIdx.x * 64;
  const int lr = tid >> 2, lc = (tid & 3) * 4;
  const int ty = tid >> 4, tx = tid & 15;
  float acc[4][4] = {};
  for (int k0 = 0; k0 < 256; k0 += 16) {
    float4 av = *(const float4*)(A  + (size_t)(row0 + lr) * 256 + k0 + lc);
    float4 bv = *(const float4*)(Bm + (size_t)(col0 + lr) * 256 + k0 + lc);
    As[lc+0][lr]=av.x; As[lc+1][lr]=av.y; As[lc+2][lr]=av.z; As[lc+3][lr]=av.w;
    Bs[lc+0][lr]=bv.x; Bs[lc+1][lr]=bv.y; Bs[lc+2][lr]=bv.z; Bs[lc+3][lr]=bv.w;
    __syncthreads();
#pragma unroll
    for (int kk = 0; kk < 16; kk++) {
      float4 a4 = *(const float4*)&As[kk][ty*4];
      float4 b4 = *(const float4*)&Bs[kk][tx*4];
      float a[4]={a4.x,a4.y,a4.z,a4.w}, bb[4]={b4.x,b4.y,b4.z,b4.w};
#pragma unroll
      for (int i = 0; i < 4; i++)
#pragma unroll
        for (int j = 0; j < 4; j++) acc[i][j] += a[i]*bb[j];
    }
    __syncthreads();
  }
#pragma unroll
  for (int i = 0; i < 4; i++)
#pragma unroll
    for (int j = 0; j < 4; j++)
      C[(size_t)(row0 + ty*4 + i) * Ssz + col0 + tx*4 + j] = acc[i][j];
}

// ---------------------------------------------------------------------------
// Prep kernels
// ---------------------------------------------------------------------------
__global__ void enc_bf_T(const float* __restrict__ enc) {
  __shared__ float tile[32][33];
  const int b = blockIdx.z, s0 = blockIdx.x * 32, k0 = blockIdx.y * 32;
  const int tx = threadIdx.x, ty = threadIdx.y;
  const float* eb = enc + (size_t)b * Ssz * Hsz;
#pragma unroll
  for (int i = 0; i < 32; i += 8)
    tile[ty + i][tx] = eb[(size_t)(s0 + ty + i) * Hsz + k0 + tx];
  __syncthreads();
  __nv_bfloat16* ob = g_encT + (size_t)b * Hsz * Ssz;
#pragma unroll
  for (int i = 0; i < 32; i += 8)
    ob[(size_t)(k0 + ty + i) * Ssz + s0 + tx] = __float2bfloat16_rn(tile[tx][ty + i]);
}

__global__ void whh_T(const float* __restrict__ W_hh) {
  __shared__ float tile[32][33];
  const int j0 = blockIdx.x * 32, k0 = blockIdx.y * 32;
  const int tx = threadIdx.x, ty = threadIdx.y;
#pragma unroll
  for (int i = 0; i < 32; i += 8)
    tile[ty + i][tx] = W_hh[(size_t)(j0 + ty + i) * Hsz + k0 + tx];
  __syncthreads();
#pragma unroll
  for (int i = 0; i < 32; i += 8)
    g_WT[(size_t)(k0 + ty + i) * G4 + j0 + tx] = tile[tx][ty + i];
}

// ---------------------------------------------------------------------------
// Kernel 2: sequential decoder. One 4-CTA cluster per batch.
// Single cluster sync per step: gates are DSMEM-exchanged during phase A,
// every CTA computes the full LSTM cell redundantly (h is CTA-local).
// (Structure identical to the proven R12 kernel; only the error bound E
//  uses the tighter per-row coefficient g_D.)
// ---------------------------------------------------------------------------
__global__ void __cluster_dims__(4, 1, 1) __launch_bounds__(512, 1)
decoder_main(const float* __restrict__ enc,
             const float* __restrict__ b_ih,
             const float* __restrict__ b_hh)
{
  extern __shared__ float sm[];
  float*  Wt        = sm;                     // KS*256 packed [k4][j][4]
  float*  h_s       = Wt + KS * 256;          // 256 (full h, local)
  float*  c_s       = h_s + 256;              // 256 (full c, local)
  float*  gates_all = c_s + 256;              // [2][1024] parity-buffered
  float*  scores_s  = gates_all + 2048;       // 256
  float*  sp        = scores_s + 256;         // 8*256 partials [kc][s]
  float*  n_sm      = sp + 2048;              // 256 (D_s per owned row)
  float*  normh_s   = n_sm + 256;             // 4
  float4* redA      = (float4*)(normh_s + 4); // 8 (u1,u2,lb,i1)
  float*  red_m     = (float*)(redA + 8);     // 8
  int*    red_i     = (int*)(red_m + 8);      // 8
  float4* tup1      = (float4*)(red_i + 8);   // [2][4]
  float*  tup2m     = (float*)(tup1 + 8);     // [2][4]
  int*    tup2i     = (int*)(tup2m + 8);      // [2][4]

  cg::cluster_group cluster = cg::this_cluster();
  const int tid  = threadIdx.x;
  const int w    = tid >> 5, lane = tid & 31;
  const int r    = blockIdx.x & 3;
  const int b    = blockIdx.x >> 2;

  // ---- init: W^T SMEM packed [k4][j][4]; CTA-owned gate cols ----
  for (int i = tid; i < KS * 256; i += 512) {
    int k = i >> 8, j = i & 255;
    int G = (j >> 6) * 256 + r * 64 + (j & 63);
    Wt[(size_t)((k >> 2) * 256 + j) * 4 + (k & 3)] = g_WT[(size_t)k * G4 + G];
  }
  float wreg[KR];
  const int jloc = (w - 8) * 32 + lane;
  const int Gj   = (jloc >> 6) * 256 + r * 64 + (jloc & 63);  // global gate idx
  if (w >= 8) {
#pragma unroll
    for (int kk = 0; kk < KR; kk++)
      wreg[kk] = g_WT[(size_t)(KS + kk) * G4 + Gj];
  }
  if (tid < 256) n_sm[tid] = g_D[b * Ssz + r * 256 + tid];

  // ---- prologue: full h(1), c(1) from bias-only gates ----
  if (tid < 256) {
    float gi = b_ih[tid]       + b_hh[tid];
    float gg = b_ih[512 + tid] + b_hh[512 + tid];
    float go = b_ih[768 + tid] + b_hh[768 + tid];
    float iv = 1.f / (1.f + expf(-gi));
    float gv = tanhf(gg);
    float ov = 1.f / (1.f + expf(-go));
    float c  = iv * gv;
    c_s[tid] = c;
    h_s[tid] = ov * tanhf(c);
  }
  __syncthreads();
  if (tid < 256 && (tid >> 6) == r)
    g_H[(size_t)b * Ssz * Hsz + tid] = h_s[tid];
  CL_ARRIVE(); CL_WAIT();   // cluster fully resident before DSMEM traffic

  const float* WXb  = g_WX + (size_t)b * Ssz * G4;
  const float* encb = enc + (size_t)b * Ssz * Hsz;

  // enc bf16 stream + permanent register cache of k-groups 0,1
  const uint4* pb = (const uint4*)(g_encT + (size_t)(b * Hsz + w * 32) * Ssz)
                    + r * 32 + lane;
  uint4 pf[8];
  if (w < 8) {
#pragma unroll
    for (int q = 0; q < 8; q++) pf[q] = pb[q * 128];
  }

  int idx = 0;

#pragma unroll 1
  for (int t = 0; t < Ssz; t++) {
    const int tp = t & 1;
    const float4* hp4 = (const float4*)h_s;

    if (w < 8) {
      // ---- bf16 scores: thread = 8 s-cols x 32 k, 3-buffer pipeline ----
      float a[8] = {0.f,0.f,0.f,0.f,0.f,0.f,0.f,0.f};
      uint4 bA[4], bB[4], bC[4];
      LDG4(bA, pb, 2); LDG4(bB, pb, 3); LDG4(bC, pb, 4);
      float4 hq;
      hq = hp4[w*8+0]; PROC4(a, (pf+0), hq);
      hq = hp4[w*8+1]; PROC4(a, (pf+4), hq);
      hq = hp4[w*8+2]; PROC4(a, bA, hq); LDG4(bA, pb, 5);
      hq = hp4[w*8+3]; PROC4(a, bB, hq); LDG4(bB, pb, 6);
      hq = hp4[w*8+4]; PROC4(a, bC, hq); LDG4(bC, pb, 7);
      hq = hp4[w*8+5]; PROC4(a, bA, hq);
      hq = hp4[w*8+6]; PROC4(a, bB, hq);
      hq = hp4[w*8+7]; PROC4(a, bC, hq);
      float4* spv = (float4*)(sp + w * 256 + lane * 8);
      spv[0] = make_float4(a[0], a[1], a[2], a[3]);
      spv[1] = make_float4(a[4], a[5], a[6], a[7]);
    } else {
      if (w == 15) {             // ||h|| for the error bound
        float s2 = 0.f;
#pragma unroll
        for (int q = 0; q < 8; q++) { float hv = h_s[lane + 32*q]; s2 += hv*hv; }
        s2 = wsum(s2);
        if (lane == 0) normh_s[0] = sqrtf(s2) * 1.01f;
      }
      // ---- fp32 gates (accumulation order bit-identical to R9) ----
      const float4* Wj = (const float4*)Wt + jloc;
      float acc0 = 0.f, acc1 = 0.f;
#pragma unroll 6
      for (int k4 = 0; k4 < KS / 4; k4++) {
        float4 wv = Wj[(size_t)k4 * 256];
        float4 hv = hp4[k4];
        acc0 += wv.x * hv.x;  acc1 += wv.y * hv.y;
        acc0 += wv.z * hv.z;  acc1 += wv.w * hv.w;
      }
#pragma unroll
      for (int q = 0; q < KR / 4; q++) {
        float4 hv = hp4[KS / 4 + q];
        acc0 += wreg[4*q + 0] * hv.x;  acc1 += wreg[4*q + 1] * hv.y;
        acc0 += wreg[4*q + 2] * hv.z;  acc1 += wreg[4*q + 3] * hv.w;
      }
      float gv_ = acc0 + acc1;
      // publish this gate value to every CTA's parity buffer
      float* gp = &gates_all[tp * 1024 + Gj];
#pragma unroll
      for (int dst = 0; dst < 4; dst++)
        *cluster.map_shared_rank(gp, dst) = gv_;
    }
    __syncthreads();

    // ---- per-CTA top-2(ub) + max(lb) over 256 s ----
    if (tid < 256) {
      const int s = tid;
      float scv = 0.f;
#pragma unroll
      for (int q = 0; q < 8; q++) scv += sp[q * 256 + s];
      scores_s[s] = scv;
      float E  = n_sm[s] * normh_s[0];
      float lb = scv - E;
      float u1 = scv + E, u2 = -INFINITY; int i1 = s;
#pragma unroll
      for (int o = 16; o; o >>= 1) {
        float ou1 = __shfl_xor_sync(0xffffffffu, u1, o);
        float ou2 = __shfl_xor_sync(0xffffffffu, u2, o);
        int   oi1 = __shfl_xor_sync(0xffffffffu, i1, o);
        float olb = __shfl_xor_sync(0xffffffffu, lb, o);
        lb = fmaxf(lb, olb);
        if (ou1 > u1) { u2 = fmaxf(u1, ou2); u1 = ou1; i1 = oi1; }
        else { u2 = fmaxf(u2, ou1); if (ou1 == u1) i1 = min(i1, oi1); }
      }
      if (lane == 0) redA[w] = make_float4(u1, u2, lb, __int_as_float(i1));
    }
    __syncthreads();

    // warp 14 (free): merge local winner, prefetch its FULL 4KB WX row to L2.
    // The global winner is one of the 4 local winners, and L2 is chip-global,
    // so the cell's WX read always hits L2.
    if (w == 14 && t < Ssz - 1) {
      float u1 = -INFINITY; int i1 = 0;
      if (lane < 8) { float4 tq = redA[lane]; u1 = tq.x; i1 = __float_as_int(tq.w); }
#pragma unroll
      for (int o = 4; o; o >>= 1) {
        float ou = __shfl_down_sync(0xffffffffu, u1, o);
        int   oi = __shfl_down_sync(0xffffffffu, i1, o);
        if (ou > u1) { u1 = ou; i1 = oi; }
      }
      i1 = __shfl_sync(0xffffffffu, i1, 0);
      const char* rowp = (const char*)(WXb + (size_t)(r * 256 + i1) * G4);
      asm volatile("prefetch.global.L2 [%0];" :: "l"(rowp + lane * 128));
    }
    if (tid == 0) {
      float4 t0 = redA[0];
      float u1 = t0.x, u2 = t0.y, lbm = t0.z; int i1 = __float_as_int(t0.w);
#pragma unroll
      for (int q = 1; q < 8; q++) {
        float4 tq = redA[q];
        lbm = fmaxf(lbm, tq.z);
        float ou1 = tq.x, ou2 = tq.y; int oi1 = __float_as_int(tq.w);
        if (ou1 > u1) { u2 = fmaxf(u1, ou2); u1 = ou1; i1 = oi1; }
        else { u2 = fmaxf(u2, ou1); if (ou1 == u1) i1 = min(i1, oi1); }
      }
      float4 pub = make_float4(u1, u2, lbm, __int_as_float(r * 256 + i1));
#pragma unroll
      for (int dst = 0; dst < 4; dst++)
        *cluster.map_shared_rank(&tup1[tp * 4 + r], dst) = pub;
    }
    CL_ARRIVE(); CL_WAIT();   // single per-step cluster sync: gates + tuples

    // ---- decide argmax (fast: unique candidate; slow: fp32 rescore) ----
    float4 q0 = tup1[tp*4+0], q1 = tup1[tp*4+1];
    float4 q2 = tup1[tp*4+2], q3 = tup1[tp*4+3];
    float L = fmaxf(fmaxf(q0.z, q1.z), fmaxf(q2.z, q3.z));
    float u1a[4] = {q0.x, q1.x, q2.x, q3.x};
    float u2a[4] = {q0.y, q1.y, q2.y, q3.y};
    float i1a[4] = {q0.w, q1.w, q2.w, q3.w};
    int cnt = 0, rstar = 0;
#pragma unroll
    for (int q = 3; q >= 0; q--)
      if (u1a[q] >= L) { cnt++; rstar = q; }
    bool fast = (cnt == 1) && (u2a[rstar] < L);

    if (fast) {
      idx = __float_as_int(i1a[rstar]);
    } else if (t < Ssz - 1) {
      // slow path (uniform cluster-wide): fp32 rescore of candidates
      if (w < 8) {
        const int s = tid;
        float E  = n_sm[s] * normh_s[0];
        float ub = scores_s[s] + E;
        unsigned mask = __ballot_sync(0xffffffffu, ub >= L);
        float best = -INFINITY; int bidx = 0x7fffffff;
        float4 h0w = hp4[lane], h1w = hp4[32 + lane];
        while (mask) {
          int bit = __ffs(mask) - 1; mask &= mask - 1;
          int s0 = w * 32 + bit;
          const float4* er = (const float4*)(encb + (size_t)(r * 256 + s0) * Hsz);
          float val = wsum(dot8(er[lane], er[32 + lane], h0w, h1w));
          if (lane == 0 && val > best) { best = val; bidx = s0; }
        }
        if (lane == 0) {
          red_m[w] = best;
          red_i[w] = (bidx == 0x7fffffff) ? 0x7fffffff : r * 256 + bidx;
        }
      }
      __syncthreads();
      if (tid == 0) {
        float gv = red_m[0]; int gi = red_i[0];
#pragma unroll
        for (int q = 1; q < 8; q++) {
          float v = red_m[q]; int ii = red_i[q];
          if (v > gv || (v == gv && ii < gi)) { gv = v; gi = ii; }
        }
#pragma unroll
        for (int dst = 0; dst < 4; dst++) {
          *cluster.map_shared_rank(&tup2m[tp * 4 + r], dst) = gv;
          *cluster.map_shared_rank(&tup2i[tp * 4 + r], dst) = gi;
        }
      }
      CL_ARRIVE(); CL_WAIT();
      float gm = tup2m[tp * 4 + 0]; idx = tup2i[tp * 4 + 0];
#pragma unroll
      for (int q = 1; q < 4; q++) {
        float mq = tup2m[tp * 4 + q]; int iq = tup2i[tp * 4 + q];
        if (mq > gm || (mq == gm && iq < idx)) { gm = mq; idx = iq; }
      }
    }

    // ---- full cell, redundant per CTA: h stays local, no broadcast ----
    if (t < Ssz - 1) {
      if (tid < 256) {
        const float* ga  = gates_all + tp * 1024;
        const float* wxr = WXb + (size_t)idx * G4 + tid;
        float gi = ga[tid]        + wxr[0];
        float gf = ga[256 + tid]  + wxr[256];
        float gg = ga[512 + tid]  + wxr[512];
        float go = ga[768 + tid]  + wxr[768];
        float iv = 1.f / (1.f + expf(-gi));
        float fv = 1.f / (1.f + expf(-gf));
        float gv = tanhf(gg);
        float ov = 1.f / (1.f + expf(-go));
        float c  = fv * c_s[tid] + iv * gv;
        c_s[tid] = c;
        float hk = ov * tanhf(c);
        h_s[tid] = hk;
        if ((tid >> 6) == r)
          g_H[((size_t)b * Ssz + t + 1) * Hsz + tid] = hk;
      }
      __syncthreads();   // h_s/c_s ready for next step (CTA-local)
    }
  }
}

// ---------------------------------------------------------------------------
// Kernel 4: softmax over out rows
// ---------------------------------------------------------------------------
__global__ __launch_bounds__(256) void softmax_finalize(float* __restrict__ out)
{
  __shared__ float rmx[8];
  __shared__ float rsm[8];
  const int tid = threadIdx.x, w = tid >> 5, lane = tid & 31;
  float4* row = (float4*)(out + (size_t)blockIdx.x * Ssz);
  float4 v = row[tid];
  float m = fmaxf(fmaxf(v.x, v.y), fmaxf(v.z, v.w));
#pragma unroll
  for (int o = 16; o; o >>= 1) m = fmaxf(m, __shfl_xor_sync(0xffffffffu, m, o));
  if (lane == 0) rmx[w] = m;
  __syncthreads();
  m = rmx[0];
#pragma unroll
  for (int q = 1; q < 8; q++) m = fmaxf(m, rmx[q]);
  float4 e;
  e.x = expf(v.x - m); e.y = expf(v.y - m);
  e.z = expf(v.z - m); e.w = expf(v.w - m);
  float s = (e.x + e.y) + (e.z + e.w);
#pragma unroll
  for (int o = 16; o; o >>= 1) s += __shfl_xor_sync(0xffffffffu, s, o);
  if (lane == 0) rsm[w] = s;
  __syncthreads();
  s = 0.f;
#pragma unroll
  for (int q = 0; q < 8; q++) s += rsm[q];
  float inv = 1.f / s;
  e.x *= inv; e.y *= inv; e.z *= inv; e.w *= inv;
  row[tid] = e;
}

// ---------------------------------------------------------------------------
extern "C" void kernel_launch(void* const* d_in, const int* in_sizes, int n_in,
                              void* d_out, int out_size)
{
  const float* enc  = (const float*)d_in[0];
  const float* W_ih = (const float*)d_in[1];
  const float* W_hh = (const float*)d_in[2];
  const float* b_ih = (const float*)d_in[3];
  const float* b_hh = (const float*)d_in[4];
  float* out = (float*)d_out;

  // preps (decoder at launch index 3 so the ncu window lands on it)
  enc_bf_T<<<dim3(Ssz / 32, Hsz / 32, Bsz), dim3(32, 8)>>>(enc);
  whh_T<<<dim3(G4 / 32, Hsz / 32), dim3(32, 8)>>>(W_hh);
  dim3 g1(G4 / 64, (Bsz * Ssz) / 64);
  wx_gemm<<<g1, 256>>>(enc, W_ih, b_ih, b_hh);

  // sequential decoder: 32 clusters x 4 CTAs x 512 threads
  const int smem_bytes = (KS * 256 + 256 + 256 + 2048 + 256 + 2048 + 256 + 4
                          + 8 * 4 + 8 + 8 + 8 * 4 + 8 + 8) * 4;
  cudaFuncSetAttribute(decoder_main,
                       cudaFuncAttributeMaxDynamicSharedMemorySize, smem_bytes);
  decoder_main<<<Bsz * 4, 512, smem_bytes>>>(enc, b_ih, b_hh);

  // probs off the critical path
  score_gemm<<<dim3(Ssz / 64, Ssz / 64, Bsz), 256>>>(enc, out);
  softmax_finalize<<<Bsz * Ssz, 256>>>(out);
}